// round 12
// baseline (speedup 1.0000x reference)
#include <cuda_runtime.h>
#include <math.h>
#include <stdint.h>

// Problem constants
#define Bsz   4
#define Sq    2048
#define Dm    512
#define Hh    8
#define DEPTH 64
#define BAND  16
#define MTOT  (Bsz * Sq)   // 8192

// Scratch (device globals: allocation-guard safe)
__device__ float g_qh[Bsz * Sq * Dm];
__device__ float g_kh[Bsz * Sq * Dm];
__device__ float g_vh[Bsz * Sq * Dm];
__device__ float g_att[Bsz * Sq * Dm];

// ---------------------------------------------------------------------------
// TF32 tensor-core GEMM (R5 proven shape, rel_err 4.2e-4, QKV 124us):
// 128x128x16 tile, 256 thr = 8 warps (2x4), warp tile 64x32, RNA cvt at store.
// Only change vs R5: BPAD 132 -> 136 (B frag banks 8c+r all-distinct).
// ---------------------------------------------------------------------------
#define BM 128
#define BN 128
#define BK 16
#define APAD 20    // A frag banks 20r+c all-distinct (proven)
#define BPAD 136   // B frag banks 8c+r all-distinct (132 was 2-way)

__device__ __forceinline__ uint32_t f2tf32(float x) {
    uint32_t r;
    asm("cvt.rna.tf32.f32 %0, %1;" : "=r"(r) : "f"(x));
    return r;
}

__device__ __forceinline__ void mma_tf32(float c[4], const uint32_t a[4], const uint32_t b[2]) {
    asm volatile(
        "mma.sync.aligned.m16n8k8.row.col.f32.tf32.tf32.f32 "
        "{%0,%1,%2,%3}, {%4,%5,%6,%7}, {%8,%9}, {%0,%1,%2,%3};"
        : "+f"(c[0]), "+f"(c[1]), "+f"(c[2]), "+f"(c[3])
        : "r"(a[0]), "r"(a[1]), "r"(a[2]), "r"(a[3]), "r"(b[0]), "r"(b[1]));
}

__device__ __forceinline__ void gemm_tf32_tile(const float* __restrict__ X,
                                               const float* __restrict__ W,
                                               const float* __restrict__ bias,
                                               float* __restrict__ Y) {
    __shared__ __align__(16) uint32_t As[2][BM][APAD];   // [buf][m][k] tf32 bits
    __shared__ __align__(16) uint32_t Bs[2][BK][BPAD];   // [buf][k][n] tf32 bits

    const int tid  = threadIdx.x;          // 0..255
    const int warp = tid >> 5;             // 0..7
    const int lane = tid & 31;
    const int wm   = warp >> 2;            // 0..1  (64-row slab)
    const int wn   = warp & 3;             // 0..3  (32-col slab)
    const int r    = lane >> 2;            // 0..7
    const int c    = lane & 3;             // 0..3

    const int rowBase = blockIdx.x * BM;
    const int colBase = blockIdx.y * BN;

    float acc[4][4][4];
#pragma unroll
    for (int mi = 0; mi < 4; mi++)
#pragma unroll
        for (int ni = 0; ni < 4; ni++)
#pragma unroll
            for (int t = 0; t < 4; t++) acc[mi][ni][t] = 0.0f;

    // R5 load assignments (coalesced)
    const int aM0 = tid >> 2;              // 0..63
    const int aM1 = aM0 + 64;
    const int aK4 = (tid & 3) * 4;
    const int bK0 = tid >> 5;              // 0..7
    const int bK1 = bK0 + 8;
    const int bN4 = (tid & 31) * 4;

    const float* Arow0 = X + (size_t)(rowBase + aM0) * Dm + aK4;
    const float* Arow1 = X + (size_t)(rowBase + aM1) * Dm + aK4;
    const float* Brow0 = W + (size_t)bK0 * Dm + colBase + bN4;
    const float* Brow1 = W + (size_t)bK1 * Dm + colBase + bN4;

    // Prologue: load tile 0 into buffer 0
    float4 a0 = *(const float4*)(Arow0);
    float4 a1 = *(const float4*)(Arow1);
    float4 b0 = *(const float4*)(Brow0);
    float4 b1 = *(const float4*)(Brow1);
    {
        uint32_t* p0 = &As[0][aM0][aK4];
        p0[0]=f2tf32(a0.x); p0[1]=f2tf32(a0.y); p0[2]=f2tf32(a0.z); p0[3]=f2tf32(a0.w);
        uint32_t* p1 = &As[0][aM1][aK4];
        p1[0]=f2tf32(a1.x); p1[1]=f2tf32(a1.y); p1[2]=f2tf32(a1.z); p1[3]=f2tf32(a1.w);
        uint32_t* q0 = &Bs[0][bK0][bN4];
        q0[0]=f2tf32(b0.x); q0[1]=f2tf32(b0.y); q0[2]=f2tf32(b0.z); q0[3]=f2tf32(b0.w);
        uint32_t* q1 = &Bs[0][bK1][bN4];
        q1[0]=f2tf32(b1.x); q1[1]=f2tf32(b1.y); q1[2]=f2tf32(b1.z); q1[3]=f2tf32(b1.w);
    }
    __syncthreads();

    const int NITER = Dm / BK;             // 32
    for (int it = 0; it < NITER; it++) {
        const int buf = it & 1;

        if (it + 1 < NITER) {
            const int koff = (it + 1) * BK;
            a0 = *(const float4*)(Arow0 + koff);
            a1 = *(const float4*)(Arow1 + koff);
            b0 = *(const float4*)(Brow0 + (size_t)koff * Dm);
            b1 = *(const float4*)(Brow1 + (size_t)koff * Dm);
        }

#pragma unroll
        for (int s = 0; s < 2; s++) {
            const int k8 = s * 8;
            uint32_t afr[4][4];
#pragma unroll
            for (int mi = 0; mi < 4; mi++) {
                const int m = wm * 64 + mi * 16 + r;
                afr[mi][0] = As[buf][m][k8 + c];
                afr[mi][1] = As[buf][m + 8][k8 + c];
                afr[mi][2] = As[buf][m][k8 + c + 4];
                afr[mi][3] = As[buf][m + 8][k8 + c + 4];
            }
            uint32_t bfr[4][2];
#pragma unroll
            for (int ni = 0; ni < 4; ni++) {
                const int n = wn * 32 + ni * 8 + r;
                bfr[ni][0] = Bs[buf][k8 + c][n];
                bfr[ni][1] = Bs[buf][k8 + c + 4][n];
            }
#pragma unroll
            for (int mi = 0; mi < 4; mi++)
#pragma unroll
                for (int ni = 0; ni < 4; ni++)
                    mma_tf32(acc[mi][ni], afr[mi], bfr[ni]);
        }

        if (it + 1 < NITER) {
            const int nb = (it + 1) & 1;
            uint32_t* p0 = &As[nb][aM0][aK4];
            p0[0]=f2tf32(a0.x); p0[1]=f2tf32(a0.y); p0[2]=f2tf32(a0.z); p0[3]=f2tf32(a0.w);
            uint32_t* p1 = &As[nb][aM1][aK4];
            p1[0]=f2tf32(a1.x); p1[1]=f2tf32(a1.y); p1[2]=f2tf32(a1.z); p1[3]=f2tf32(a1.w);
            uint32_t* q0 = &Bs[nb][bK0][bN4];
            q0[0]=f2tf32(b0.x); q0[1]=f2tf32(b0.y); q0[2]=f2tf32(b0.z); q0[3]=f2tf32(b0.w);
            uint32_t* q1 = &Bs[nb][bK1][bN4];
            q1[0]=f2tf32(b1.x); q1[1]=f2tf32(b1.y); q1[2]=f2tf32(b1.z); q1[3]=f2tf32(b1.w);
        }
        __syncthreads();
    }

    // Epilogue: bias + store
#pragma unroll
    for (int mi = 0; mi < 4; mi++) {
        const int row0 = rowBase + wm * 64 + mi * 16 + r;
#pragma unroll
        for (int ni = 0; ni < 4; ni++) {
            const int col = colBase + wn * 32 + ni * 8 + c * 2;
            const float2 bv = *(const float2*)(bias + col);
            float2 v0 = make_float2(acc[mi][ni][0] + bv.x, acc[mi][ni][1] + bv.y);
            float2 v1 = make_float2(acc[mi][ni][2] + bv.x, acc[mi][ni][3] + bv.y);
            *(float2*)(Y + (size_t)row0 * Dm + col) = v0;
            *(float2*)(Y + (size_t)(row0 + 8) * Dm + col) = v1;
        }
    }
}

// Fused QKV projection: z-dim selects (input, weight, bias, dest)
__global__ __launch_bounds__(256, 2) void qkv_proj_kernel(
    const float* __restrict__ q, const float* __restrict__ k, const float* __restrict__ v,
    const float* __restrict__ wq, const float* __restrict__ bq,
    const float* __restrict__ wk, const float* __restrict__ bk,
    const float* __restrict__ wv, const float* __restrict__ bv) {
    const float *X, *W, *bias;
    float* Y;
    if (blockIdx.z == 0)      { X = q; W = wq; bias = bq; Y = g_qh; }
    else if (blockIdx.z == 1) { X = k; W = wk; bias = bk; Y = g_kh; }
    else                      { X = v; W = wv; bias = bv; Y = g_vh; }
    gemm_tf32_tile(X, W, bias, Y);
}

__global__ __launch_bounds__(256, 2) void out_proj_kernel(
    const float* __restrict__ wo, const float* __restrict__ bo,
    float* __restrict__ out) {
    gemm_tf32_tile(g_att, wo, bo, out);
}

// ---------------------------------------------------------------------------
// Banded attention, two-phase, shfl-free.
// Phase 1: threads = (query, key-lane): each computes <=5 full 64-depth dots
//          (independent chains, float4 smem loads) -> Es[q][w] = exp(logit) or 0.
// Phase 2: threads = (query, depth-slice): O = (sum_w e_w * V_w) / (sum_w e_w).
// Plain exp is exact softmax here (logits tiny); masked keys contribute e=0.
// All smem row strides = 68 floats = 272 B (16-byte aligned for float4;
// 66 was the R11 misaligned-address bug).
// ---------------------------------------------------------------------------
#define QB   32
#define KW   (QB + 2 * BAND)   // 64-key window
#define KSTA 68                // Ks/Qs/Vs stride: float4-aligned (272 B)
#define EST  36                // Es stride

__global__ __launch_bounds__(256, 4) void band_attn_kernel() {
    __shared__ float Ks[KW][KSTA];
    __shared__ float Vs[KW][KSTA];
    __shared__ float Qs[QB][KSTA];
    __shared__ float Es[QB][EST];

    const int tid = threadIdx.x;
    const int q0  = blockIdx.x * QB;
    const int h   = blockIdx.y;
    const int b   = blockIdx.z;
    const size_t base = (size_t)b * Sq * Dm + (size_t)h * DEPTH;

    // Phase 0: cooperative loads.
    // K/V window: 64 keys x 64 depth = 1024 float4
#pragma unroll
    for (int u = 0; u < 4; u++) {
        const int idx = tid + u * 256;
        const int row = idx >> 4;          // 0..63
        const int col = (idx & 15) * 4;
        const int key = q0 - BAND + row;
        float4 k4 = make_float4(0.f, 0.f, 0.f, 0.f);
        float4 v4 = make_float4(0.f, 0.f, 0.f, 0.f);
        if (key >= 0 && key < Sq) {
            k4 = *(const float4*)(g_kh + base + (size_t)key * Dm + col);
            v4 = *(const float4*)(g_vh + base + (size_t)key * Dm + col);
        }
        *(float4*)&Ks[row][col] = k4;
        *(float4*)&Vs[row][col] = v4;
    }
    // Q tile: 32 x 64 = 512 float4
#pragma unroll
    for (int u = 0; u < 2; u++) {
        const int idx = tid + u * 256;
        const int row = idx >> 4;          // 0..31
        const int col = (idx & 15) * 4;
        *(float4*)&Qs[row][col] =
            *(const float4*)(g_qh + base + (size_t)(q0 + row) * Dm + col);
    }
    __syncthreads();

    const int qi = tid >> 3;            // query 0..31
    const int ki = tid & 7;             // key lane 0..7
    const int gq = q0 + qi;
    const float scale = 0.125f;         // 1/sqrt(64)

    // Phase 1: logits. Thread computes keys w = ki + 8t, t = 0..4 (w < 33).
    {
        float accd[5] = {0.f, 0.f, 0.f, 0.f, 0.f};
#pragma unroll
        for (int d4 = 0; d4 < 16; d4++) {
            const float4 q4 = *(const float4*)&Qs[qi][d4 * 4];
#pragma unroll
            for (int t = 0; t < 5; t++) {
                const int w = ki + 8 * t;
                if (w < 33) {
                    const float4 k4 = *(const float4*)&Ks[qi + w][d4 * 4];
                    accd[t] += q4.x * k4.x + q4.y * k4.y + q4.z * k4.z + q4.w * k4.w;
                }
            }
        }
#pragma unroll
        for (int t = 0; t < 5; t++) {
            const int w = ki + 8 * t;
            if (w < 33) {
                const int j = gq - BAND + w;
                const float e = ((unsigned)j < (unsigned)Sq) ? __expf(accd[t] * scale) : 0.0f;
                Es[qi][w] = e;
            }
        }
    }
    __syncthreads();

    // Phase 2: V accumulation. Thread = (query qi2, 8-float depth slice).
    {
        const int qi2 = tid >> 3;
        const int ds  = (tid & 7) * 8;
        float l = 0.0f;
        float4 acc0 = make_float4(0.f, 0.f, 0.f, 0.f);
        float4 acc1 = make_float4(0.f, 0.f, 0.f, 0.f);
#pragma unroll
        for (int w = 0; w < 33; w++) {
            const float e = Es[qi2][w];
            l += e;
            const float4 v0 = *(const float4*)&Vs[qi2 + w][ds];
            const float4 v1 = *(const float4*)&Vs[qi2 + w][ds + 4];
            acc0.x += e * v0.x; acc0.y += e * v0.y; acc0.z += e * v0.z; acc0.w += e * v0.w;
            acc1.x += e * v1.x; acc1.y += e * v1.y; acc1.z += e * v1.z; acc1.w += e * v1.w;
        }
        const float inv = 1.0f / l;
        acc0.x *= inv; acc0.y *= inv; acc0.z *= inv; acc0.w *= inv;
        acc1.x *= inv; acc1.y *= inv; acc1.z *= inv; acc1.w *= inv;
        float* op = g_att + base + (size_t)(q0 + qi2) * Dm + ds;
        *(float4*)(op)     = acc0;
        *(float4*)(op + 4) = acc1;
    }
}

// ---------------------------------------------------------------------------
extern "C" void kernel_launch(void* const* d_in, const int* in_sizes, int n_in,
                              void* d_out, int out_size) {
    const float* q  = (const float*)d_in[0];
    const float* k  = (const float*)d_in[1];
    const float* v  = (const float*)d_in[2];
    const float* wq = (const float*)d_in[3];
    const float* bq = (const float*)d_in[4];
    const float* wk = (const float*)d_in[5];
    const float* bk = (const float*)d_in[6];
    const float* wv = (const float*)d_in[7];
    const float* bv = (const float*)d_in[8];
    const float* wo = (const float*)d_in[9];
    const float* bo = (const float*)d_in[10];
    float* out = (float*)d_out;

    dim3 gridQKV(MTOT / BM, Dm / BN, 3);      // 64 x 4 x 3
    qkv_proj_kernel<<<gridQKV, 256>>>(q, k, v, wq, bq, wk, bk, wv, bv);

    dim3 gridAtt(Sq / QB, Hh, Bsz);           // 64 x 8 x 4
    band_attn_kernel<<<gridAtt, 256>>>();

    dim3 gridOut(MTOT / BM, Dm / BN, 1);      // 64 x 4
    out_proj_kernel<<<gridOut, 256>>>(wo, bo, out);
}

// round 14
// speedup vs baseline: 1.6224x; 1.6224x over previous
#include <cuda_runtime.h>
#include <math.h>
#include <stdint.h>

// Problem constants
#define Bsz   4
#define Sq    2048
#define Dm    512
#define Hh    8
#define DEPTH 64
#define BAND  16
#define MTOT  (Bsz * Sq)   // 8192
#define WELEM (Dm * Dm)    // 262144 elements per weight matrix

// Scratch (device globals: allocation-guard safe)
__device__ float    g_qh[Bsz * Sq * Dm];
__device__ float    g_kh[Bsz * Sq * Dm];
__device__ float    g_vh[Bsz * Sq * Dm];
__device__ float    g_att[Bsz * Sq * Dm];
__device__ uint32_t g_wt[4 * WELEM];     // pre-converted tf32 bits: wq, wk, wv, wo

__device__ __forceinline__ uint32_t f2tf32(float x) {
    uint32_t r;
    asm("cvt.rna.tf32.f32 %0, %1;" : "=r"(r) : "f"(x));
    return r;
}

// ---------------------------------------------------------------------------
// Weight pre-conversion: fp32 -> tf32 (RNA) bits, once per launch.
// 4 x 512 x 512 = 1M elements = 262144 float4. Grid 1024 x 256.
// ---------------------------------------------------------------------------
__global__ void conv_w_kernel(const float* __restrict__ wq, const float* __restrict__ wk,
                              const float* __restrict__ wv, const float* __restrict__ wo) {
    const int i   = blockIdx.x * blockDim.x + threadIdx.x;   // float4 index
    const int mat = i >> 16;                                 // 65536 float4 per matrix
    const int off = (i & 65535) * 4;
    const float* src = (mat == 0) ? wq : (mat == 1) ? wk : (mat == 2) ? wv : wo;
    const float4 w4 = *(const float4*)(src + off);
    uint4 o;
    o.x = f2tf32(w4.x); o.y = f2tf32(w4.y); o.z = f2tf32(w4.z); o.w = f2tf32(w4.w);
    *(uint4*)&g_wt[mat * WELEM + off] = o;
}

// ---------------------------------------------------------------------------
// TF32 tensor-core GEMM: Y[M x 512] = X[M x 512] @ W[512 x 512] + bias.
// R5 proven shape: 128x128x16 tile, 256 thr = 8 warps (2x4), warp tile 64x32.
// A-side: LDG.128 + RNA cvt + STS.128 (vectorized; was 8x STS.32).
// B-side: cp.async.cg of PRE-ROUNDED tf32 bits from g_wt (no cvt, no STS,
//         no staging regs; numerics bit-identical to R5 since rounding
//         already applied by conv_w_kernel).
// APAD 20: A frag banks 20r+c all-distinct. BPAD 136: B frag banks 8c+r
// all-distinct; cp.async dsts consecutive 16B/lane (conflict-free).
// ---------------------------------------------------------------------------
#define BM 128
#define BN 128
#define BK 16
#define APAD 20
#define BPAD 136

__device__ __forceinline__ uint32_t smem_u32(const void* p) {
    return (uint32_t)__cvta_generic_to_shared(p);
}
#define CP_ASYNC16(dst_u32, src_ptr) \
    asm volatile("cp.async.cg.shared.global [%0], [%1], 16;" :: "r"(dst_u32), "l"(src_ptr))
#define CP_COMMIT()  asm volatile("cp.async.commit_group;" ::: "memory")
#define CP_WAIT0()   asm volatile("cp.async.wait_group 0;" ::: "memory")

__device__ __forceinline__ void mma_tf32(float c[4], const uint32_t a[4], const uint32_t b[2]) {
    asm volatile(
        "mma.sync.aligned.m16n8k8.row.col.f32.tf32.tf32.f32 "
        "{%0,%1,%2,%3}, {%4,%5,%6,%7}, {%8,%9}, {%0,%1,%2,%3};"
        : "+f"(c[0]), "+f"(c[1]), "+f"(c[2]), "+f"(c[3])
        : "r"(a[0]), "r"(a[1]), "r"(a[2]), "r"(a[3]), "r"(b[0]), "r"(b[1]));
}

__device__ __forceinline__ void gemm_tf32_tile(const float* __restrict__ X,
                                               const uint32_t* __restrict__ Wt,
                                               const float* __restrict__ bias,
                                               float* __restrict__ Y) {
    __shared__ __align__(16) uint32_t As[2][BM][APAD];   // [buf][m][k] tf32 bits
    __shared__ __align__(16) uint32_t Bs[2][BK][BPAD];   // [buf][k][n] tf32 bits

    const int tid  = threadIdx.x;          // 0..255
    const int warp = tid >> 5;             // 0..7
    const int lane = tid & 31;
    const int wm   = warp >> 2;            // 0..1  (64-row slab)
    const int wn   = warp & 3;             // 0..3  (32-col slab)
    const int r    = lane >> 2;            // 0..7
    const int c    = lane & 3;             // 0..3

    const int rowBase = blockIdx.x * BM;
    const int colBase = blockIdx.y * BN;

    float acc[4][4][4];
#pragma unroll
    for (int mi = 0; mi < 4; mi++)
#pragma unroll
        for (int ni = 0; ni < 4; ni++)
#pragma unroll
            for (int t = 0; t < 4; t++) acc[mi][ni][t] = 0.0f;

    // Load assignments (R5, coalesced)
    const int aM0 = tid >> 2;              // 0..63
    const int aM1 = aM0 + 64;
    const int aK4 = (tid & 3) * 4;
    const int bK0 = tid >> 5;              // 0..7
    const int bK1 = bK0 + 8;
    const int bN4 = (tid & 31) * 4;

    const float*    Arow0 = X  + (size_t)(rowBase + aM0) * Dm + aK4;
    const float*    Arow1 = X  + (size_t)(rowBase + aM1) * Dm + aK4;
    const uint32_t* Brow0 = Wt + (size_t)bK0 * Dm + colBase + bN4;
    const uint32_t* Brow1 = Wt + (size_t)bK1 * Dm + colBase + bN4;

    // Prologue: stage 0
    {
        CP_ASYNC16(smem_u32(&Bs[0][bK0][bN4]), Brow0);
        CP_ASYNC16(smem_u32(&Bs[0][bK1][bN4]), Brow1);
        CP_COMMIT();
        const float4 a0 = *(const float4*)(Arow0);
        const float4 a1 = *(const float4*)(Arow1);
        uint4 p0, p1;
        p0.x = f2tf32(a0.x); p0.y = f2tf32(a0.y); p0.z = f2tf32(a0.z); p0.w = f2tf32(a0.w);
        p1.x = f2tf32(a1.x); p1.y = f2tf32(a1.y); p1.z = f2tf32(a1.z); p1.w = f2tf32(a1.w);
        *(uint4*)&As[0][aM0][aK4] = p0;
        *(uint4*)&As[0][aM1][aK4] = p1;
        CP_WAIT0();
    }
    __syncthreads();

    const int NITER = Dm / BK;             // 32
    float4 a0, a1;
    for (int it = 0; it < NITER; it++) {
        const int buf = it & 1;

        if (it + 1 < NITER) {
            const size_t koff = (size_t)(it + 1) * BK;
            CP_ASYNC16(smem_u32(&Bs[(it + 1) & 1][bK0][bN4]), Brow0 + koff * Dm);
            CP_ASYNC16(smem_u32(&Bs[(it + 1) & 1][bK1][bN4]), Brow1 + koff * Dm);
            CP_COMMIT();
            a0 = *(const float4*)(Arow0 + koff);
            a1 = *(const float4*)(Arow1 + koff);
        }

#pragma unroll
        for (int s = 0; s < 2; s++) {
            const int k8 = s * 8;
            uint32_t afr[4][4];
#pragma unroll
            for (int mi = 0; mi < 4; mi++) {
                const int m = wm * 64 + mi * 16 + r;
                afr[mi][0] = As[buf][m][k8 + c];
                afr[mi][1] = As[buf][m + 8][k8 + c];
                afr[mi][2] = As[buf][m][k8 + c + 4];
                afr[mi][3] = As[buf][m + 8][k8 + c + 4];
            }
            uint32_t bfr[4][2];
#pragma unroll
            for (int ni = 0; ni < 4; ni++) {
                const int n = wn * 32 + ni * 8 + r;
                bfr[ni][0] = Bs[buf][k8 + c][n];
                bfr[ni][1] = Bs[buf][k8 + c + 4][n];
            }
#pragma unroll
            for (int mi = 0; mi < 4; mi++)
#pragma unroll
                for (int ni = 0; ni < 4; ni++)
                    mma_tf32(acc[mi][ni], afr[mi], bfr[ni]);
        }

        if (it + 1 < NITER) {
            const int nb = (it + 1) & 1;
            uint4 p0, p1;
            p0.x = f2tf32(a0.x); p0.y = f2tf32(a0.y); p0.z = f2tf32(a0.z); p0.w = f2tf32(a0.w);
            p1.x = f2tf32(a1.x); p1.y = f2tf32(a1.y); p1.z = f2tf32(a1.z); p1.w = f2tf32(a1.w);
            *(uint4*)&As[nb][aM0][aK4] = p0;
            *(uint4*)&As[nb][aM1][aK4] = p1;
            CP_WAIT0();
        }
        __syncthreads();
    }

    // Epilogue: bias + store
#pragma unroll
    for (int mi = 0; mi < 4; mi++) {
        const int row0 = rowBase + wm * 64 + mi * 16 + r;
#pragma unroll
        for (int ni = 0; ni < 4; ni++) {
            const int col = colBase + wn * 32 + ni * 8 + c * 2;
            const float2 bv = *(const float2*)(bias + col);
            float2 v0 = make_float2(acc[mi][ni][0] + bv.x, acc[mi][ni][1] + bv.y);
            float2 v1 = make_float2(acc[mi][ni][2] + bv.x, acc[mi][ni][3] + bv.y);
            *(float2*)(Y + (size_t)row0 * Dm + col) = v0;
            *(float2*)(Y + (size_t)(row0 + 8) * Dm + col) = v1;
        }
    }
}

// Fused QKV projection: z-dim selects (input, weight, bias, dest)
__global__ __launch_bounds__(256, 2) void qkv_proj_kernel(
    const float* __restrict__ q, const float* __restrict__ k, const float* __restrict__ v,
    const float* __restrict__ bq, const float* __restrict__ bk, const float* __restrict__ bv) {
    const float *X, *bias;
    float* Y;
    if (blockIdx.z == 0)      { X = q; bias = bq; Y = g_qh; }
    else if (blockIdx.z == 1) { X = k; bias = bk; Y = g_kh; }
    else                      { X = v; bias = bv; Y = g_vh; }
    gemm_tf32_tile(X, g_wt + (size_t)blockIdx.z * WELEM, bias, Y);
}

__global__ __launch_bounds__(256, 2) void out_proj_kernel(
    const float* __restrict__ bo, float* __restrict__ out) {
    gemm_tf32_tile(g_att, g_wt + 3ull * WELEM, bo, out);
}

// ---------------------------------------------------------------------------
// Banded attention, two-phase, shfl-free (R12, passed).
// ---------------------------------------------------------------------------
#define QB   32
#define KW   (QB + 2 * BAND)   // 64-key window
#define KSTA 68                // float4-aligned stride (272 B)
#define EST  36

__global__ __launch_bounds__(256, 4) void band_attn_kernel() {
    __shared__ float Ks[KW][KSTA];
    __shared__ float Vs[KW][KSTA];
    __shared__ float Qs[QB][KSTA];
    __shared__ float Es[QB][EST];

    const int tid = threadIdx.x;
    const int q0  = blockIdx.x * QB;
    const int h   = blockIdx.y;
    const int b   = blockIdx.z;
    const size_t base = (size_t)b * Sq * Dm + (size_t)h * DEPTH;

#pragma unroll
    for (int u = 0; u < 4; u++) {
        const int idx = tid + u * 256;
        const int row = idx >> 4;
        const int col = (idx & 15) * 4;
        const int key = q0 - BAND + row;
        float4 k4 = make_float4(0.f, 0.f, 0.f, 0.f);
        float4 v4 = make_float4(0.f, 0.f, 0.f, 0.f);
        if (key >= 0 && key < Sq) {
            k4 = *(const float4*)(g_kh + base + (size_t)key * Dm + col);
            v4 = *(const float4*)(g_vh + base + (size_t)key * Dm + col);
        }
        *(float4*)&Ks[row][col] = k4;
        *(float4*)&Vs[row][col] = v4;
    }
#pragma unroll
    for (int u = 0; u < 2; u++) {
        const int idx = tid + u * 256;
        const int row = idx >> 4;
        const int col = (idx & 15) * 4;
        *(float4*)&Qs[row][col] =
            *(const float4*)(g_qh + base + (size_t)(q0 + row) * Dm + col);
    }
    __syncthreads();

    const int qi = tid >> 3;
    const int ki = tid & 7;
    const int gq = q0 + qi;
    const float scale = 0.125f;

    // Phase 1: logits -> Es
    {
        float accd[5] = {0.f, 0.f, 0.f, 0.f, 0.f};
#pragma unroll
        for (int d4 = 0; d4 < 16; d4++) {
            const float4 q4 = *(const float4*)&Qs[qi][d4 * 4];
#pragma unroll
            for (int t = 0; t < 5; t++) {
                const int w = ki + 8 * t;
                if (w < 33) {
                    const float4 k4 = *(const float4*)&Ks[qi + w][d4 * 4];
                    accd[t] += q4.x * k4.x + q4.y * k4.y + q4.z * k4.z + q4.w * k4.w;
                }
            }
        }
#pragma unroll
        for (int t = 0; t < 5; t++) {
            const int w = ki + 8 * t;
            if (w < 33) {
                const int j = gq - BAND + w;
                Es[qi][w] = ((unsigned)j < (unsigned)Sq) ? __expf(accd[t] * scale) : 0.0f;
            }
        }
    }
    __syncthreads();

    // Phase 2: V accumulation
    {
        const int qi2 = tid >> 3;
        const int ds  = (tid & 7) * 8;
        float l = 0.0f;
        float4 acc0 = make_float4(0.f, 0.f, 0.f, 0.f);
        float4 acc1 = make_float4(0.f, 0.f, 0.f, 0.f);
#pragma unroll
        for (int w = 0; w < 33; w++) {
            const float e = Es[qi2][w];
            l += e;
            const float4 v0 = *(const float4*)&Vs[qi2 + w][ds];
            const float4 v1 = *(const float4*)&Vs[qi2 + w][ds + 4];
            acc0.x += e * v0.x; acc0.y += e * v0.y; acc0.z += e * v0.z; acc0.w += e * v0.w;
            acc1.x += e * v1.x; acc1.y += e * v1.y; acc1.z += e * v1.z; acc1.w += e * v1.w;
        }
        const float inv = 1.0f / l;
        acc0.x *= inv; acc0.y *= inv; acc0.z *= inv; acc0.w *= inv;
        acc1.x *= inv; acc1.y *= inv; acc1.z *= inv; acc1.w *= inv;
        float* op = g_att + base + (size_t)(q0 + qi2) * Dm + ds;
        *(float4*)(op)     = acc0;
        *(float4*)(op + 4) = acc1;
    }
}

// ---------------------------------------------------------------------------
extern "C" void kernel_launch(void* const* d_in, const int* in_sizes, int n_in,
                              void* d_out, int out_size) {
    const float* q  = (const float*)d_in[0];
    const float* k  = (const float*)d_in[1];
    const float* v  = (const float*)d_in[2];
    const float* wq = (const float*)d_in[3];
    const float* bq = (const float*)d_in[4];
    const float* wk = (const float*)d_in[5];
    const float* bk = (const float*)d_in[6];
    const float* wv = (const float*)d_in[7];
    const float* bv = (const float*)d_in[8];
    const float* wo = (const float*)d_in[9];
    const float* bo = (const float*)d_in[10];
    float* out = (float*)d_out;

    conv_w_kernel<<<1024, 256>>>(wq, wk, wv, wo);

    dim3 gridQKV(MTOT / BM, Dm / BN, 3);      // 64 x 4 x 3
    qkv_proj_kernel<<<gridQKV, 256>>>(q, k, v, bq, bk, bv);

    dim3 gridAtt(Sq / QB, Hh, Bsz);           // 64 x 8 x 4
    band_attn_kernel<<<gridAtt, 256>>>();

    dim3 gridOut(MTOT / BM, Dm / BN, 1);      // 64 x 4
    out_proj_kernel<<<gridOut, 256>>>(bo, out);
}

// round 15
// speedup vs baseline: 1.6557x; 1.0206x over previous
#include <cuda_runtime.h>
#include <math.h>
#include <stdint.h>

// Problem constants
#define Bsz   4
#define Sq    2048
#define Dm    512
#define Hh    8
#define DEPTH 64
#define BAND  16
#define MTOT  (Bsz * Sq)   // 8192
#define WELEM (Dm * Dm)    // 262144 elements per weight matrix

// Scratch (device globals: allocation-guard safe)
__device__ float    g_qh[Bsz * Sq * Dm];
__device__ float    g_kh[Bsz * Sq * Dm];
__device__ float    g_vh[Bsz * Sq * Dm];
__device__ float    g_att[Bsz * Sq * Dm];
__device__ uint32_t g_wt[4 * WELEM];     // pre-converted tf32 bits: wq, wk, wv, wo

__device__ __forceinline__ uint32_t f2tf32(float x) {
    uint32_t r;
    asm("cvt.rna.tf32.f32 %0, %1;" : "=r"(r) : "f"(x));
    return r;
}

// ---------------------------------------------------------------------------
// Weight pre-conversion: fp32 -> tf32 (RNA) bits, once per launch.
// ---------------------------------------------------------------------------
__global__ void conv_w_kernel(const float* __restrict__ wq, const float* __restrict__ wk,
                              const float* __restrict__ wv, const float* __restrict__ wo) {
    const int i   = blockIdx.x * blockDim.x + threadIdx.x;   // float4 index
    const int mat = i >> 16;                                 // 65536 float4 per matrix
    const int off = (i & 65535) * 4;
    const float* src = (mat == 0) ? wq : (mat == 1) ? wk : (mat == 2) ? wv : wo;
    const float4 w4 = *(const float4*)(src + off);
    uint4 o;
    o.x = f2tf32(w4.x); o.y = f2tf32(w4.y); o.z = f2tf32(w4.z); o.w = f2tf32(w4.w);
    *(uint4*)&g_wt[mat * WELEM + off] = o;
}

// ---------------------------------------------------------------------------
// TF32 tensor-core GEMM: Y[M x 512] = X[M x 512] @ W[512 x 512] + bias.
// 128x128x16 tile, 256 thr = 8 warps (2x4), warp tile 64x32.
// A-side: LDG.128 + RNA cvt + STS.128; fragments via ldmatrix.m8n8.x4
//   (1 instr replaces 16 LDS.32; b16 8x8 mapping == tf32 frag mapping).
// B-side: cp.async.cg of pre-rounded tf32 bits from g_wt; frags via LDS.32
//   (BPAD 136: banks 8c+r all-distinct).
// ---------------------------------------------------------------------------
#define BM 128
#define BN 128
#define BK 16
#define APAD 20
#define BPAD 136

__device__ __forceinline__ uint32_t smem_u32(const void* p) {
    return (uint32_t)__cvta_generic_to_shared(p);
}
#define CP_ASYNC16(dst_u32, src_ptr) \
    asm volatile("cp.async.cg.shared.global [%0], [%1], 16;" :: "r"(dst_u32), "l"(src_ptr))
#define CP_COMMIT()  asm volatile("cp.async.commit_group;" ::: "memory")
#define CP_WAIT0()   asm volatile("cp.async.wait_group 0;" ::: "memory")

__device__ __forceinline__ void ldsm4(uint32_t& r0, uint32_t& r1, uint32_t& r2, uint32_t& r3,
                                      uint32_t addr) {
    asm volatile("ldmatrix.sync.aligned.m8n8.x4.shared.b16 {%0,%1,%2,%3}, [%4];"
                 : "=r"(r0), "=r"(r1), "=r"(r2), "=r"(r3) : "r"(addr));
}

__device__ __forceinline__ void mma_tf32(float c[4], const uint32_t a[4], const uint32_t b[2]) {
    asm volatile(
        "mma.sync.aligned.m16n8k8.row.col.f32.tf32.tf32.f32 "
        "{%0,%1,%2,%3}, {%4,%5,%6,%7}, {%8,%9}, {%0,%1,%2,%3};"
        : "+f"(c[0]), "+f"(c[1]), "+f"(c[2]), "+f"(c[3])
        : "r"(a[0]), "r"(a[1]), "r"(a[2]), "r"(a[3]), "r"(b[0]), "r"(b[1]));
}

__device__ __forceinline__ void gemm_tf32_tile(const float* __restrict__ X,
                                               const uint32_t* __restrict__ Wt,
                                               const float* __restrict__ bias,
                                               float* __restrict__ Y) {
    __shared__ __align__(16) uint32_t As[2][BM][APAD];   // [buf][m][k] tf32 bits
    __shared__ __align__(16) uint32_t Bs[2][BK][BPAD];   // [buf][k][n] tf32 bits

    const int tid  = threadIdx.x;          // 0..255
    const int warp = tid >> 5;             // 0..7
    const int lane = tid & 31;
    const int wm   = warp >> 2;            // 0..1  (64-row slab)
    const int wn   = warp & 3;             // 0..3  (32-col slab)
    const int r    = lane >> 2;            // 0..7
    const int c    = lane & 3;             // 0..3

    const int rowBase = blockIdx.x * BM;
    const int colBase = blockIdx.y * BN;

    float acc[4][4][4];
#pragma unroll
    for (int mi = 0; mi < 4; mi++)
#pragma unroll
        for (int ni = 0; ni < 4; ni++)
#pragma unroll
            for (int t = 0; t < 4; t++) acc[mi][ni][t] = 0.0f;

    // ldmatrix A addressing: per mi, 4 matrices (m0/m0+8) x (k8/k8+4).
    // Thread -> (row, col-quad):
    const int lmRow = (lane & 7) + ((lane >> 3) & 1) * 8;   // 0..15 within 16-row tile
    const int lmCol = (lane >> 4) * 4;                      // 0 or 4

    // Load assignments (coalesced)
    const int aM0 = tid >> 2;              // 0..63
    const int aM1 = aM0 + 64;
    const int aK4 = (tid & 3) * 4;
    const int bK0 = tid >> 5;              // 0..7
    const int bK1 = bK0 + 8;
    const int bN4 = (tid & 31) * 4;

    const float*    Arow0 = X  + (size_t)(rowBase + aM0) * Dm + aK4;
    const float*    Arow1 = X  + (size_t)(rowBase + aM1) * Dm + aK4;
    const uint32_t* Brow0 = Wt + (size_t)bK0 * Dm + colBase + bN4;
    const uint32_t* Brow1 = Wt + (size_t)bK1 * Dm + colBase + bN4;

    // Prologue: stage 0
    {
        CP_ASYNC16(smem_u32(&Bs[0][bK0][bN4]), Brow0);
        CP_ASYNC16(smem_u32(&Bs[0][bK1][bN4]), Brow1);
        CP_COMMIT();
        const float4 a0 = *(const float4*)(Arow0);
        const float4 a1 = *(const float4*)(Arow1);
        uint4 p0, p1;
        p0.x = f2tf32(a0.x); p0.y = f2tf32(a0.y); p0.z = f2tf32(a0.z); p0.w = f2tf32(a0.w);
        p1.x = f2tf32(a1.x); p1.y = f2tf32(a1.y); p1.z = f2tf32(a1.z); p1.w = f2tf32(a1.w);
        *(uint4*)&As[0][aM0][aK4] = p0;
        *(uint4*)&As[0][aM1][aK4] = p1;
        CP_WAIT0();
    }
    __syncthreads();

    const int NITER = Dm / BK;             // 32
    float4 a0, a1;
    for (int it = 0; it < NITER; it++) {
        const int buf = it & 1;

        if (it + 1 < NITER) {
            const size_t koff = (size_t)(it + 1) * BK;
            CP_ASYNC16(smem_u32(&Bs[(it + 1) & 1][bK0][bN4]), Brow0 + koff * Dm);
            CP_ASYNC16(smem_u32(&Bs[(it + 1) & 1][bK1][bN4]), Brow1 + koff * Dm);
            CP_COMMIT();
            a0 = *(const float4*)(Arow0 + koff);
            a1 = *(const float4*)(Arow1 + koff);
        }

#pragma unroll
        for (int s = 0; s < 2; s++) {
            const int k8 = s * 8;
            uint32_t afr[4][4];
#pragma unroll
            for (int mi = 0; mi < 4; mi++) {
                const int m = wm * 64 + mi * 16 + lmRow;
                ldsm4(afr[mi][0], afr[mi][1], afr[mi][2], afr[mi][3],
                      smem_u32(&As[buf][m][k8 + lmCol]));
            }
            uint32_t bfr[4][2];
#pragma unroll
            for (int ni = 0; ni < 4; ni++) {
                const int n = wn * 32 + ni * 8 + r;
                bfr[ni][0] = Bs[buf][k8 + c][n];
                bfr[ni][1] = Bs[buf][k8 + c + 4][n];
            }
#pragma unroll
            for (int mi = 0; mi < 4; mi++)
#pragma unroll
                for (int ni = 0; ni < 4; ni++)
                    mma_tf32(acc[mi][ni], afr[mi], bfr[ni]);
        }

        if (it + 1 < NITER) {
            const int nb = (it + 1) & 1;
            uint4 p0, p1;
            p0.x = f2tf32(a0.x); p0.y = f2tf32(a0.y); p0.z = f2tf32(a0.z); p0.w = f2tf32(a0.w);
            p1.x = f2tf32(a1.x); p1.y = f2tf32(a1.y); p1.z = f2tf32(a1.z); p1.w = f2tf32(a1.w);
            *(uint4*)&As[nb][aM0][aK4] = p0;
            *(uint4*)&As[nb][aM1][aK4] = p1;
            CP_WAIT0();
        }
        __syncthreads();
    }

    // Epilogue: bias + store
#pragma unroll
    for (int mi = 0; mi < 4; mi++) {
        const int row0 = rowBase + wm * 64 + mi * 16 + r;
#pragma unroll
        for (int ni = 0; ni < 4; ni++) {
            const int col = colBase + wn * 32 + ni * 8 + c * 2;
            const float2 bv = *(const float2*)(bias + col);
            float2 v0 = make_float2(acc[mi][ni][0] + bv.x, acc[mi][ni][1] + bv.y);
            float2 v1 = make_float2(acc[mi][ni][2] + bv.x, acc[mi][ni][3] + bv.y);
            *(float2*)(Y + (size_t)row0 * Dm + col) = v0;
            *(float2*)(Y + (size_t)(row0 + 8) * Dm + col) = v1;
        }
    }
}

// Fused QKV projection: z-dim selects (input, weight, bias, dest)
__global__ __launch_bounds__(256, 2) void qkv_proj_kernel(
    const float* __restrict__ q, const float* __restrict__ k, const float* __restrict__ v,
    const float* __restrict__ bq, const float* __restrict__ bk, const float* __restrict__ bv) {
    const float *X, *bias;
    float* Y;
    if (blockIdx.z == 0)      { X = q; bias = bq; Y = g_qh; }
    else if (blockIdx.z == 1) { X = k; bias = bk; Y = g_kh; }
    else                      { X = v; bias = bv; Y = g_vh; }
    gemm_tf32_tile(X, g_wt + (size_t)blockIdx.z * WELEM, bias, Y);
}

__global__ __launch_bounds__(256, 2) void out_proj_kernel(
    const float* __restrict__ bo, float* __restrict__ out) {
    gemm_tf32_tile(g_att, g_wt + 3ull * WELEM, bo, out);
}

// ---------------------------------------------------------------------------
// Banded attention, two-phase, shfl-free (R12/R14, passed).
// ---------------------------------------------------------------------------
#define QB   32
#define KW   (QB + 2 * BAND)   // 64-key window
#define KSTA 68                // float4-aligned stride (272 B)
#define EST  36

__global__ __launch_bounds__(256, 4) void band_attn_kernel() {
    __shared__ float Ks[KW][KSTA];
    __shared__ float Vs[KW][KSTA];
    __shared__ float Qs[QB][KSTA];
    __shared__ float Es[QB][EST];

    const int tid = threadIdx.x;
    const int q0  = blockIdx.x * QB;
    const int h   = blockIdx.y;
    const int b   = blockIdx.z;
    const size_t base = (size_t)b * Sq * Dm + (size_t)h * DEPTH;

#pragma unroll
    for (int u = 0; u < 4; u++) {
        const int idx = tid + u * 256;
        const int row = idx >> 4;
        const int col = (idx & 15) * 4;
        const int key = q0 - BAND + row;
        float4 k4 = make_float4(0.f, 0.f, 0.f, 0.f);
        float4 v4 = make_float4(0.f, 0.f, 0.f, 0.f);
        if (key >= 0 && key < Sq) {
            k4 = *(const float4*)(g_kh + base + (size_t)key * Dm + col);
            v4 = *(const float4*)(g_vh + base + (size_t)key * Dm + col);
        }
        *(float4*)&Ks[row][col] = k4;
        *(float4*)&Vs[row][col] = v4;
    }
#pragma unroll
    for (int u = 0; u < 2; u++) {
        const int idx = tid + u * 256;
        const int row = idx >> 4;
        const int col = (idx & 15) * 4;
        *(float4*)&Qs[row][col] =
            *(const float4*)(g_qh + base + (size_t)(q0 + row) * Dm + col);
    }
    __syncthreads();

    const int qi = tid >> 3;
    const int ki = tid & 7;
    const int gq = q0 + qi;
    const float scale = 0.125f;

    // Phase 1: logits -> Es
    {
        float accd[5] = {0.f, 0.f, 0.f, 0.f, 0.f};
#pragma unroll
        for (int d4 = 0; d4 < 16; d4++) {
            const float4 q4 = *(const float4*)&Qs[qi][d4 * 4];
#pragma unroll
            for (int t = 0; t < 5; t++) {
                const int w = ki + 8 * t;
                if (w < 33) {
                    const float4 k4 = *(const float4*)&Ks[qi + w][d4 * 4];
                    accd[t] += q4.x * k4.x + q4.y * k4.y + q4.z * k4.z + q4.w * k4.w;
                }
            }
        }
#pragma unroll
        for (int t = 0; t < 5; t++) {
            const int w = ki + 8 * t;
            if (w < 33) {
                const int j = gq - BAND + w;
                Es[qi][w] = ((unsigned)j < (unsigned)Sq) ? __expf(accd[t] * scale) : 0.0f;
            }
        }
    }
    __syncthreads();

    // Phase 2: V accumulation
    {
        const int qi2 = tid >> 3;
        const int ds  = (tid & 7) * 8;
        float l = 0.0f;
        float4 acc0 = make_float4(0.f, 0.f, 0.f, 0.f);
        float4 acc1 = make_float4(0.f, 0.f, 0.f, 0.f);
#pragma unroll
        for (int w = 0; w < 33; w++) {
            const float e = Es[qi2][w];
            l += e;
            const float4 v0 = *(const float4*)&Vs[qi2 + w][ds];
            const float4 v1 = *(const float4*)&Vs[qi2 + w][ds + 4];
            acc0.x += e * v0.x; acc0.y += e * v0.y; acc0.z += e * v0.z; acc0.w += e * v0.w;
            acc1.x += e * v1.x; acc1.y += e * v1.y; acc1.z += e * v1.z; acc1.w += e * v1.w;
        }
        const float inv = 1.0f / l;
        acc0.x *= inv; acc0.y *= inv; acc0.z *= inv; acc0.w *= inv;
        acc1.x *= inv; acc1.y *= inv; acc1.z *= inv; acc1.w *= inv;
        float* op = g_att + base + (size_t)(q0 + qi2) * Dm + ds;
        *(float4*)(op)     = acc0;
        *(float4*)(op + 4) = acc1;
    }
}

// ---------------------------------------------------------------------------
extern "C" void kernel_launch(void* const* d_in, const int* in_sizes, int n_in,
                              void* d_out, int out_size) {
    const float* q  = (const float*)d_in[0];
    const float* k  = (const float*)d_in[1];
    const float* v  = (const float*)d_in[2];
    const float* wq = (const float*)d_in[3];
    const float* bq = (const float*)d_in[4];
    const float* wk = (const float*)d_in[5];
    const float* bk = (const float*)d_in[6];
    const float* wv = (const float*)d_in[7];
    const float* bv = (const float*)d_in[8];
    const float* wo = (const float*)d_in[9];
    const float* bo = (const float*)d_in[10];
    float* out = (float*)d_out;

    conv_w_kernel<<<1024, 256>>>(wq, wk, wv, wo);

    dim3 gridQKV(MTOT / BM, Dm / BN, 3);      // 64 x 4 x 3
    qkv_proj_kernel<<<gridQKV, 256>>>(q, k, v, bq, bk, bv);

    dim3 gridAtt(Sq / QB, Hh, Bsz);           // 64 x 8 x 4
    band_attn_kernel<<<gridAtt, 256>>>();

    dim3 gridOut(MTOT / BM, Dm / BN, 1);      // 64 x 4
    out_proj_kernel<<<gridOut, 256>>>(bo, out);
}

// round 16
// speedup vs baseline: 1.6563x; 1.0003x over previous
#include <cuda_runtime.h>
#include <math.h>
#include <stdint.h>

// Problem constants
#define Bsz   4
#define Sq    2048
#define Dm    512
#define Hh    8
#define DEPTH 64
#define BAND  16
#define MTOT  (Bsz * Sq)   // 8192
#define WELEM (Dm * Dm)    // 262144 elements per weight matrix

// Scratch (device globals: allocation-guard safe)
__device__ float    g_qh[Bsz * Sq * Dm];
__device__ float    g_kh[Bsz * Sq * Dm];
__device__ float    g_vh[Bsz * Sq * Dm];
__device__ float    g_att[Bsz * Sq * Dm];
__device__ uint32_t g_wt[4 * WELEM];     // pre-converted tf32 bits: wq, wk, wv, wo

__device__ __forceinline__ uint32_t f2tf32(float x) {
    uint32_t r;
    asm("cvt.rna.tf32.f32 %0, %1;" : "=r"(r) : "f"(x));
    return r;
}

// ---------------------------------------------------------------------------
// Weight pre-conversion: fp32 -> tf32 (RNA) bits, once per launch.
// ---------------------------------------------------------------------------
__global__ void conv_w_kernel(const float* __restrict__ wq, const float* __restrict__ wk,
                              const float* __restrict__ wv, const float* __restrict__ wo) {
    const int i   = blockIdx.x * blockDim.x + threadIdx.x;   // float4 index
    const int mat = i >> 16;                                 // 65536 float4 per matrix
    const int off = (i & 65535) * 4;
    const float* src = (mat == 0) ? wq : (mat == 1) ? wk : (mat == 2) ? wv : wo;
    const float4 w4 = *(const float4*)(src + off);
    uint4 o;
    o.x = f2tf32(w4.x); o.y = f2tf32(w4.y); o.z = f2tf32(w4.z); o.w = f2tf32(w4.w);
    *(uint4*)&g_wt[mat * WELEM + off] = o;
}

// ---------------------------------------------------------------------------
// TF32 tensor-core GEMM: Y[M x 512] = X[M x 512] @ W[512 x 512] + bias.
// 128x128x16 tile, 256 thr = 8 warps (2x4), warp tile 64x32.
// PIPELINE FIX vs R14/R15: B is 3-stage cp.async with wait_group 1 (the old
// loop committed g(it+1) then wait_group 0 -- draining the group it had just
// issued, exposing full L2 latency every iteration; tensor pipe capped ~36%).
// Structure per iter: WAIT1 -> bar -> issue cp for stage it+2 -> compute
// stage it -> store A for stage it+1. All buffer-reuse races protected by the
// single barrier (targets were consumed at it-1; every warp crossed BAR(it)).
// A-side: 2-stage LDG + RNA cvt + STS.128 (rounding before MMA is mandatory,
// R10 lesson); fragments via ldmatrix.m8n8.x4. B frag LDS: banks 8c+r.
// Smem 46.6 KB static, 2 CTAs/SM.
// ---------------------------------------------------------------------------
#define BM 128
#define BN 128
#define BK 16
#define APAD 20
#define BPAD 136

__device__ __forceinline__ uint32_t smem_u32(const void* p) {
    return (uint32_t)__cvta_generic_to_shared(p);
}
#define CP_ASYNC16(dst_u32, src_ptr) \
    asm volatile("cp.async.cg.shared.global [%0], [%1], 16;" :: "r"(dst_u32), "l"(src_ptr))
#define CP_COMMIT()  asm volatile("cp.async.commit_group;" ::: "memory")
#define CP_WAIT1()   asm volatile("cp.async.wait_group 1;" ::: "memory")
#define CP_WAIT0()   asm volatile("cp.async.wait_group 0;" ::: "memory")

__device__ __forceinline__ void ldsm4(uint32_t& r0, uint32_t& r1, uint32_t& r2, uint32_t& r3,
                                      uint32_t addr) {
    asm volatile("ldmatrix.sync.aligned.m8n8.x4.shared.b16 {%0,%1,%2,%3}, [%4];"
                 : "=r"(r0), "=r"(r1), "=r"(r2), "=r"(r3) : "r"(addr));
}

__device__ __forceinline__ void mma_tf32(float c[4], const uint32_t a[4], const uint32_t b[2]) {
    asm volatile(
        "mma.sync.aligned.m16n8k8.row.col.f32.tf32.tf32.f32 "
        "{%0,%1,%2,%3}, {%4,%5,%6,%7}, {%8,%9}, {%0,%1,%2,%3};"
        : "+f"(c[0]), "+f"(c[1]), "+f"(c[2]), "+f"(c[3])
        : "r"(a[0]), "r"(a[1]), "r"(a[2]), "r"(a[3]), "r"(b[0]), "r"(b[1]));
}

__device__ __forceinline__ void gemm_tf32_tile(const float* __restrict__ X,
                                               const uint32_t* __restrict__ Wt,
                                               const float* __restrict__ bias,
                                               float* __restrict__ Y) {
    __shared__ __align__(16) uint32_t As[2][BM][APAD];   // [stage%2][m][k] tf32 bits
    __shared__ __align__(16) uint32_t Bs[3][BK][BPAD];   // [stage%3][k][n] tf32 bits

    const int tid  = threadIdx.x;          // 0..255
    const int warp = tid >> 5;             // 0..7
    const int lane = tid & 31;
    const int wm   = warp >> 2;            // 0..1  (64-row slab)
    const int wn   = warp & 3;             // 0..3  (32-col slab)
    const int r    = lane >> 2;            // 0..7
    const int c    = lane & 3;             // 0..3

    const int rowBase = blockIdx.x * BM;
    const int colBase = blockIdx.y * BN;

    float acc[4][4][4];
#pragma unroll
    for (int mi = 0; mi < 4; mi++)
#pragma unroll
        for (int ni = 0; ni < 4; ni++)
#pragma unroll
            for (int t = 0; t < 4; t++) acc[mi][ni][t] = 0.0f;

    // ldmatrix A addressing
    const int lmRow = (lane & 7) + ((lane >> 3) & 1) * 8;   // 0..15 within 16-row tile
    const int lmCol = (lane >> 4) * 4;                      // 0 or 4

    // Load assignments (coalesced)
    const int aM0 = tid >> 2;              // 0..63
    const int aM1 = aM0 + 64;
    const int aK4 = (tid & 3) * 4;
    const int bK0 = tid >> 5;              // 0..7
    const int bK1 = bK0 + 8;
    const int bN4 = (tid & 31) * 4;

    const float*    Arow0 = X  + (size_t)(rowBase + aM0) * Dm + aK4;
    const float*    Arow1 = X  + (size_t)(rowBase + aM1) * Dm + aK4;
    const uint32_t* Brow0 = Wt + (size_t)bK0 * Dm + colBase + bN4;
    const uint32_t* Brow1 = Wt + (size_t)bK1 * Dm + colBase + bN4;

    // Prologue: B stages 0 and 1 in flight; A stage 0 in smem.
    CP_ASYNC16(smem_u32(&Bs[0][bK0][bN4]), Brow0);
    CP_ASYNC16(smem_u32(&Bs[0][bK1][bN4]), Brow1);
    CP_COMMIT();
    CP_ASYNC16(smem_u32(&Bs[1][bK0][bN4]), Brow0 + (size_t)BK * Dm);
    CP_ASYNC16(smem_u32(&Bs[1][bK1][bN4]), Brow1 + (size_t)BK * Dm);
    CP_COMMIT();
    {
        const float4 a0 = *(const float4*)(Arow0);
        const float4 a1 = *(const float4*)(Arow1);
        uint4 p0, p1;
        p0.x = f2tf32(a0.x); p0.y = f2tf32(a0.y); p0.z = f2tf32(a0.z); p0.w = f2tf32(a0.w);
        p1.x = f2tf32(a1.x); p1.y = f2tf32(a1.y); p1.z = f2tf32(a1.z); p1.w = f2tf32(a1.w);
        *(uint4*)&As[0][aM0][aK4] = p0;
        *(uint4*)&As[0][aM1][aK4] = p1;
    }

    const int NITER = Dm / BK;             // 32
    for (int it = 0; it < NITER; it++) {
        const int bs  = it % 3;
        const int as_ = it & 1;

        // Ensure stage `it` B data landed; keep stage it+1 in flight.
        if (it < NITER - 1) CP_WAIT1(); else CP_WAIT0();
        __syncthreads();   // visibility of B stage it + A stores from it-1;
                           // also: all warps finished compute(it-1), so stage
                           // reuse below is race-free.

        // Issue B for stage it+2 (targets (it-1)%3, consumed at it-1).
        if (it + 2 < NITER) {
            const size_t koff = (size_t)(it + 2) * BK;
            CP_ASYNC16(smem_u32(&Bs[(it + 2) % 3][bK0][bN4]), Brow0 + koff * Dm);
            CP_ASYNC16(smem_u32(&Bs[(it + 2) % 3][bK1][bN4]), Brow1 + koff * Dm);
            CP_COMMIT();
        }
        // A global loads for stage it+1 (latency covered by compute below).
        float4 a0n, a1n;
        if (it + 1 < NITER) {
            const size_t koff = (size_t)(it + 1) * BK;
            a0n = *(const float4*)(Arow0 + koff);
            a1n = *(const float4*)(Arow1 + koff);
        }

        // Compute on stage it.
#pragma unroll
        for (int s = 0; s < 2; s++) {
            const int k8 = s * 8;
            uint32_t afr[4][4];
#pragma unroll
            for (int mi = 0; mi < 4; mi++) {
                const int m = wm * 64 + mi * 16 + lmRow;
                ldsm4(afr[mi][0], afr[mi][1], afr[mi][2], afr[mi][3],
                      smem_u32(&As[as_][m][k8 + lmCol]));
            }
            uint32_t bfr[4][2];
#pragma unroll
            for (int ni = 0; ni < 4; ni++) {
                const int n = wn * 32 + ni * 8 + r;
                bfr[ni][0] = Bs[bs][k8 + c][n];
                bfr[ni][1] = Bs[bs][k8 + c + 4][n];
            }
#pragma unroll
            for (int mi = 0; mi < 4; mi++)
#pragma unroll
                for (int ni = 0; ni < 4; ni++)
                    mma_tf32(acc[mi][ni], afr[mi], bfr[ni]);
        }

        // Store A for stage it+1 (targets buffer consumed at it-1).
        if (it + 1 < NITER) {
            const int na = (it + 1) & 1;
            uint4 p0, p1;
            p0.x = f2tf32(a0n.x); p0.y = f2tf32(a0n.y); p0.z = f2tf32(a0n.z); p0.w = f2tf32(a0n.w);
            p1.x = f2tf32(a1n.x); p1.y = f2tf32(a1n.y); p1.z = f2tf32(a1n.z); p1.w = f2tf32(a1n.w);
            *(uint4*)&As[na][aM0][aK4] = p0;
            *(uint4*)&As[na][aM1][aK4] = p1;
        }
    }

    // Epilogue: bias + store
#pragma unroll
    for (int mi = 0; mi < 4; mi++) {
        const int row0 = rowBase + wm * 64 + mi * 16 + r;
#pragma unroll
        for (int ni = 0; ni < 4; ni++) {
            const int col = colBase + wn * 32 + ni * 8 + c * 2;
            const float2 bv = *(const float2*)(bias + col);
            float2 v0 = make_float2(acc[mi][ni][0] + bv.x, acc[mi][ni][1] + bv.y);
            float2 v1 = make_float2(acc[mi][ni][2] + bv.x, acc[mi][ni][3] + bv.y);
            *(float2*)(Y + (size_t)row0 * Dm + col) = v0;
            *(float2*)(Y + (size_t)(row0 + 8) * Dm + col) = v1;
        }
    }
}

// Fused QKV projection: z-dim selects (input, weight, bias, dest)
__global__ __launch_bounds__(256, 2) void qkv_proj_kernel(
    const float* __restrict__ q, const float* __restrict__ k, const float* __restrict__ v,
    const float* __restrict__ bq, const float* __restrict__ bk, const float* __restrict__ bv) {
    const float *X, *bias;
    float* Y;
    if (blockIdx.z == 0)      { X = q; bias = bq; Y = g_qh; }
    else if (blockIdx.z == 1) { X = k; bias = bk; Y = g_kh; }
    else                      { X = v; bias = bv; Y = g_vh; }
    gemm_tf32_tile(X, g_wt + (size_t)blockIdx.z * WELEM, bias, Y);
}

__global__ __launch_bounds__(256, 2) void out_proj_kernel(
    const float* __restrict__ bo, float* __restrict__ out) {
    gemm_tf32_tile(g_att, g_wt + 3ull * WELEM, bo, out);
}

// ---------------------------------------------------------------------------
// Banded attention, two-phase, shfl-free (R12/R14/R15, passed).
// ---------------------------------------------------------------------------
#define QB   32
#define KW   (QB + 2 * BAND)   // 64-key window
#define KSTA 68                // float4-aligned stride (272 B)
#define EST  36

__global__ __launch_bounds__(256, 4) void band_attn_kernel() {
    __shared__ float Ks[KW][KSTA];
    __shared__ float Vs[KW][KSTA];
    __shared__ float Qs[QB][KSTA];
    __shared__ float Es[QB][EST];

    const int tid = threadIdx.x;
    const int q0  = blockIdx.x * QB;
    const int h   = blockIdx.y;
    const int b   = blockIdx.z;
    const size_t base = (size_t)b * Sq * Dm + (size_t)h * DEPTH;

#pragma unroll
    for (int u = 0; u < 4; u++) {
        const int idx = tid + u * 256;
        const int row = idx >> 4;
        const int col = (idx & 15) * 4;
        const int key = q0 - BAND + row;
        float4 k4 = make_float4(0.f, 0.f, 0.f, 0.f);
        float4 v4 = make_float4(0.f, 0.f, 0.f, 0.f);
        if (key >= 0 && key < Sq) {
            k4 = *(const float4*)(g_kh + base + (size_t)key * Dm + col);
            v4 = *(const float4*)(g_vh + base + (size_t)key * Dm + col);
        }
        *(float4*)&Ks[row][col] = k4;
        *(float4*)&Vs[row][col] = v4;
    }
#pragma unroll
    for (int u = 0; u < 2; u++) {
        const int idx = tid + u * 256;
        const int row = idx >> 4;
        const int col = (idx & 15) * 4;
        *(float4*)&Qs[row][col] =
            *(const float4*)(g_qh + base + (size_t)(q0 + row) * Dm + col);
    }
    __syncthreads();

    const int qi = tid >> 3;
    const int ki = tid & 7;
    const int gq = q0 + qi;
    const float scale = 0.125f;

    // Phase 1: logits -> Es
    {
        float accd[5] = {0.f, 0.f, 0.f, 0.f, 0.f};
#pragma unroll
        for (int d4 = 0; d4 < 16; d4++) {
            const float4 q4 = *(const float4*)&Qs[qi][d4 * 4];
#pragma unroll
            for (int t = 0; t < 5; t++) {
                const int w = ki + 8 * t;
                if (w < 33) {
                    const float4 k4 = *(const float4*)&Ks[qi + w][d4 * 4];
                    accd[t] += q4.x * k4.x + q4.y * k4.y + q4.z * k4.z + q4.w * k4.w;
                }
            }
        }
#pragma unroll
        for (int t = 0; t < 5; t++) {
            const int w = ki + 8 * t;
            if (w < 33) {
                const int j = gq - BAND + w;
                Es[qi][w] = ((unsigned)j < (unsigned)Sq) ? __expf(accd[t] * scale) : 0.0f;
            }
        }
    }
    __syncthreads();

    // Phase 2: V accumulation
    {
        const int qi2 = tid >> 3;
        const int ds  = (tid & 7) * 8;
        float l = 0.0f;
        float4 acc0 = make_float4(0.f, 0.f, 0.f, 0.f);
        float4 acc1 = make_float4(0.f, 0.f, 0.f, 0.f);
#pragma unroll
        for (int w = 0; w < 33; w++) {
            const float e = Es[qi2][w];
            l += e;
            const float4 v0 = *(const float4*)&Vs[qi2 + w][ds];
            const float4 v1 = *(const float4*)&Vs[qi2 + w][ds + 4];
            acc0.x += e * v0.x; acc0.y += e * v0.y; acc0.z += e * v0.z; acc0.w += e * v0.w;
            acc1.x += e * v1.x; acc1.y += e * v1.y; acc1.z += e * v1.z; acc1.w += e * v1.w;
        }
        const float inv = 1.0f / l;
        acc0.x *= inv; acc0.y *= inv; acc0.z *= inv; acc0.w *= inv;
        acc1.x *= inv; acc1.y *= inv; acc1.z *= inv; acc1.w *= inv;
        float* op = g_att + base + (size_t)(q0 + qi2) * Dm + ds;
        *(float4*)(op)     = acc0;
        *(float4*)(op + 4) = acc1;
    }
}

// ---------------------------------------------------------------------------
extern "C" void kernel_launch(void* const* d_in, const int* in_sizes, int n_in,
                              void* d_out, int out_size) {
    const float* q  = (const float*)d_in[0];
    const float* k  = (const float*)d_in[1];
    const float* v  = (const float*)d_in[2];
    const float* wq = (const float*)d_in[3];
    const float* bq = (const float*)d_in[4];
    const float* wk = (const float*)d_in[5];
    const float* bk = (const float*)d_in[6];
    const float* wv = (const float*)d_in[7];
    const float* bv = (const float*)d_in[8];
    const float* wo = (const float*)d_in[9];
    const float* bo = (const float*)d_in[10];
    float* out = (float*)d_out;

    conv_w_kernel<<<1024, 256>>>(wq, wk, wv, wo);

    dim3 gridQKV(MTOT / BM, Dm / BN, 3);      // 64 x 4 x 3
    qkv_proj_kernel<<<gridQKV, 256>>>(q, k, v, bq, bk, bv);

    dim3 gridAtt(Sq / QB, Hh, Bsz);           // 64 x 8 x 4
    band_attn_kernel<<<gridAtt, 256>>>();

    dim3 gridOut(MTOT / BM, Dm / BN, 1);      // 64 x 4
    out_proj_kernel<<<gridOut, 256>>>(bo, out);
}